// round 2
// baseline (speedup 1.0000x reference)
#include <cuda_runtime.h>
#include <cuda_bf16.h>
#include <cstdint>
#include <cstddef>

// Problem dims
#define BB    64
#define CC    512
#define HWS   784
#define MTOT  (BB * HWS)        // 50176
#define MTILE 128
#define NTILE 128
#define KCH   64                // K chunk
#define NCHNK (CC / KCH)        // 8

// smem layout (bytes):
//   stages: 2 x { A[128][72] bf16 (18432B), B[128][72] bf16 (18432B) } = 73728
//   fp32 D tile reuses [0, 66048) after mainloop
//   params at 73728: 5 x 128 f32 = 2560
#define ROWB     144u           // 72 bf16 = 144B padded row
#define ASTAGE   18432u
#define STAGEB   36864u
#define SMPAR    73728u
#define SMTOTAL  76288u
#define TPITCH   129            // f32 words per D-tile row

// ---------------- scratch (static device globals; no runtime alloc) ----------------
__device__ __nv_bfloat16 g_a[(size_t)MTOT * CC];   // binarized activations, [M][K]
__device__ __nv_bfloat16 g_wb[CC * CC];            // sign(W), [N][K]
__device__ float g_alpha[CC];
__device__ float g_beta2[CC];

// ---------------- helpers (baseline PTX only: sm_75/sm_80 features) ----------------
static __device__ __forceinline__ uint32_t smem_u32(const void* p) {
    uint32_t a;
    asm("{ .reg .u64 t; cvta.to.shared.u64 t, %1; cvt.u32.u64 %0, t; }" : "=r"(a) : "l"(p));
    return a;
}
static __device__ __forceinline__ void cp16(uint32_t s, const void* g) {
    asm volatile("cp.async.cg.shared.global [%0], [%1], 16;" :: "r"(s), "l"(g) : "memory");
}
#define CP_COMMIT() asm volatile("cp.async.commit_group;" ::: "memory")
#define CP_WAIT(n)  asm volatile("cp.async.wait_group %0;" :: "n"(n) : "memory")

static __device__ __forceinline__ void ldsm4(uint32_t* r, uint32_t a) {
    asm volatile("ldmatrix.sync.aligned.m8n8.x4.shared.b16 {%0,%1,%2,%3}, [%4];"
                 : "=r"(r[0]), "=r"(r[1]), "=r"(r[2]), "=r"(r[3]) : "r"(a));
}
static __device__ __forceinline__ void ldsm2(uint32_t* r, uint32_t a) {
    asm volatile("ldmatrix.sync.aligned.m8n8.x2.shared.b16 {%0,%1}, [%2];"
                 : "=r"(r[0]), "=r"(r[1]) : "r"(a));
}
static __device__ __forceinline__ void mma16816(float* c, const uint32_t* a, const uint32_t* b) {
    asm volatile(
        "mma.sync.aligned.m16n8k16.row.col.f32.bf16.bf16.f32 "
        "{%0,%1,%2,%3}, {%4,%5,%6,%7}, {%8,%9}, {%0,%1,%2,%3};"
        : "+f"(c[0]), "+f"(c[1]), "+f"(c[2]), "+f"(c[3])
        : "r"(a[0]), "r"(a[1]), "r"(a[2]), "r"(a[3]), "r"(b[0]), "r"(b[1]));
}

// ---------------- kernel 1: per-channel epilogue constants ----------------
__global__ void prep_kernel(const float* __restrict__ W, const float* __restrict__ gam,
                            const float* __restrict__ bet, const float* __restrict__ mea,
                            const float* __restrict__ var) {
    int wid = threadIdx.x >> 5, lane = threadIdx.x & 31;
    int o = blockIdx.x * 8 + wid;
    const float* wr = W + (size_t)o * CC;
    float s = 0.f;
    #pragma unroll
    for (int j = 0; j < 16; j++) s += fabsf(wr[lane + j * 32]);
    #pragma unroll
    for (int off = 16; off > 0; off >>= 1) s += __shfl_xor_sync(0xffffffffu, s, off);
    if (lane == 0) {
        float scale = s * (1.0f / 512.0f);
        float A = gam[o] * rsqrtf(var[o] + 1e-5f);
        g_alpha[o] = A * scale;
        g_beta2[o] = bet[o] - A * mea[o];
    }
}

// ---------------- kernel 2: Wb = sign(W) as bf16 (+-1) ----------------
__global__ void sign_w_kernel(const float* __restrict__ W) {
    int i = blockIdx.x * blockDim.x + threadIdx.x;   // 131072 threads, 2 elems each
    float2 v = reinterpret_cast<const float2*>(W)[i];
    uint32_t p = ((v.x >= 0.f) ? 0x3F80u : 0xBF80u) |
                 (((v.y >= 0.f) ? 0x3F80u : 0xBF80u) << 16);
    reinterpret_cast<uint32_t*>(g_wb)[i] = p;
}

// ---------------- kernel 3: binarize x + transpose NCHW -> [M][K] bf16 ----------------
__global__ void binarize_kernel(const float* __restrict__ x, const float* __restrict__ rb) {
    __shared__ unsigned short ts[64][66];
    int b   = blockIdx.z;
    int k0  = blockIdx.y * 64;
    int hw0 = blockIdx.x * 64;
    int tid = threadIdx.x;

    #pragma unroll
    for (int i = 0; i < 16; i++) {
        int idx = tid + i * 256;
        int cc = idx >> 6, hh = idx & 63;
        int hw = hw0 + hh;
        if (hw < HWS) {
            float v = x[(size_t)((b << 9) + k0 + cc) * HWS + hw] + rb[k0 + cc];
            ts[hh][cc] = (v >= 0.f) ? 0x3F80 : 0xBF80;
        }
    }
    __syncthreads();
    #pragma unroll
    for (int i = 0; i < 8; i++) {
        int j = tid + i * 256;
        int hh = j >> 5, c2 = (j & 31) * 2;
        int hw = hw0 + hh;
        if (hw < HWS) {
            uint32_t v = (uint32_t)ts[hh][c2] | ((uint32_t)ts[hh][c2 + 1] << 16);
            *reinterpret_cast<uint32_t*>(&g_a[(size_t)(b * HWS + hw) * CC + k0 + c2]) = v;
        }
    }
}

// ---------------- kernel 4: mma.sync GEMM + fused BN/residual/RPReLU ----------------
__global__ void __launch_bounds__(256, 2)
gemm_kernel(const float* __restrict__ x, const float* __restrict__ slope,
            const float* __restrict__ shift, const float* __restrict__ pbias,
            float* __restrict__ out)
{
    extern __shared__ char smem[];
    const uint32_t sb = smem_u32(smem);
    const int tid = threadIdx.x, wid = tid >> 5, lane = tid & 31;
    const int m0 = blockIdx.y * MTILE;
    const int n0 = blockIdx.x * NTILE;

    float* alphaS = reinterpret_cast<float*>(smem + SMPAR);
    float* betaS  = alphaS + 128;
    float* slopeS = alphaS + 256;
    float* shiftS = alphaS + 384;
    float* pbiasS = alphaS + 512;
    if (tid < 128) {
        alphaS[tid] = g_alpha[n0 + tid];
        betaS[tid]  = g_beta2[n0 + tid];
        slopeS[tid] = slope[n0 + tid];
        shiftS[tid] = shift[n0 + tid];
        pbiasS[tid] = pbias[n0 + tid];
    }

    const int ldrow = tid >> 3;           // 0..31 (x8 iters -> 128 rows via +32)
    const int ldseg = tid & 7;            // 16B segment within 128B of k-chunk

    // prologue: stage 0 <- chunk 0
    {
        const char* ga = (const char*)g_a  + ((size_t)m0 * CC) * 2 + ldseg * 16;
        const char* gb = (const char*)g_wb + ((size_t)n0 * CC) * 2 + ldseg * 16;
        #pragma unroll
        for (int j = 0; j < 4; j++) {
            int row = ldrow + j * 32;
            cp16(sb + row * ROWB + ldseg * 16,          ga + (size_t)row * (CC * 2));
            cp16(sb + ASTAGE + row * ROWB + ldseg * 16, gb + (size_t)row * (CC * 2));
        }
        CP_COMMIT();
    }

    float acc[4][4][4] = {};
    const int mw = (wid >> 2) * 64;
    const int nw = (wid & 3) * 32;

    // ldmatrix lane addressing (byte offsets within a stage matrix)
    const int aRowSel = (lane & 7) + ((lane >> 3) & 1) * 8;   // row within 16-row tile
    const int aColSel = ((lane >> 4) & 1) * 8;                // k offset 0/8
    const int bRowSel = (lane & 7);
    const int bColSel = ((lane >> 3) & 1) * 8;

    for (int c = 0; c < NCHNK; c++) {
        const int st = c & 1;
        if (c < NCHNK - 1) {
            const int cn = c + 1;
            const uint32_t so = (uint32_t)(st ^ 1) * STAGEB;
            const char* ga = (const char*)g_a  + ((size_t)m0 * CC + cn * KCH) * 2 + ldseg * 16;
            const char* gb = (const char*)g_wb + ((size_t)n0 * CC + cn * KCH) * 2 + ldseg * 16;
            #pragma unroll
            for (int j = 0; j < 4; j++) {
                int row = ldrow + j * 32;
                cp16(sb + so + row * ROWB + ldseg * 16,          ga + (size_t)row * (CC * 2));
                cp16(sb + so + ASTAGE + row * ROWB + ldseg * 16, gb + (size_t)row * (CC * 2));
            }
            CP_COMMIT();
            CP_WAIT(1);
        } else {
            CP_WAIT(0);
        }
        __syncthreads();

        const uint32_t aBase = sb + (uint32_t)st * STAGEB;
        const uint32_t bBase = aBase + ASTAGE;
        #pragma unroll
        for (int ks = 0; ks < 4; ks++) {
            uint32_t af[4][4], bf[4][2];
            #pragma unroll
            for (int mt = 0; mt < 4; mt++) {
                int r = mw + mt * 16 + aRowSel;
                ldsm4(af[mt], aBase + r * ROWB + (ks * 16 + aColSel) * 2);
            }
            #pragma unroll
            for (int nt = 0; nt < 4; nt++) {
                int r = nw + nt * 8 + bRowSel;
                ldsm2(bf[nt], bBase + r * ROWB + (ks * 16 + bColSel) * 2);
            }
            #pragma unroll
            for (int mt = 0; mt < 4; mt++)
                #pragma unroll
                for (int nt = 0; nt < 4; nt++)
                    mma16816(acc[mt][nt], af[mt], bf[nt]);
        }
        __syncthreads();
    }

    // ---- stage D through smem (reuses stage area) ----
    float* tile = reinterpret_cast<float*>(smem);
    const int dr = lane >> 2;           // 0..7
    const int dc = (lane & 3) * 2;      // 0,2,4,6
    #pragma unroll
    for (int mt = 0; mt < 4; mt++) {
        #pragma unroll
        for (int nt = 0; nt < 4; nt++) {
            int r = mw + mt * 16 + dr;
            int cc2 = nw + nt * 8 + dc;
            tile[r * TPITCH + cc2]           = acc[mt][nt][0];
            tile[r * TPITCH + cc2 + 1]       = acc[mt][nt][1];
            tile[(r + 8) * TPITCH + cc2]     = acc[mt][nt][2];
            tile[(r + 8) * TPITCH + cc2 + 1] = acc[mt][nt][3];
        }
    }
    __syncthreads();

    // ---- epilogue: BN + residual + RPReLU, coalesced over hw ----
    #pragma unroll 4
    for (int g = 0; g < 16; g++) {
        const int nl = wid + 8 * g;
        const int n = n0 + nl;
        const float al = alphaS[nl], be = betaS[nl];
        const float sl = slopeS[nl], sh = shiftS[nl], pb = pbiasS[nl];
        #pragma unroll
        for (int j = 0; j < 4; j++) {
            int ml = lane + 32 * j;
            int m = m0 + ml;
            int b = m / HWS;
            int hw = m - b * HWS;
            size_t gi = ((size_t)(b * CC + n)) * HWS + hw;
            float raw = tile[ml * TPITCH + nl];
            float sv = fmaf(al, raw, be) + x[gi];
            float t = sv - sh;
            out[gi] = ((t > 0.f) ? t : sl * t) + pb;
        }
    }
}

// ---------------- launch ----------------
extern "C" void kernel_launch(void* const* d_in, const int* in_sizes, int n_in,
                              void* d_out, int out_size) {
    const float* x   = (const float*)d_in[0];
    const float* rb  = (const float*)d_in[1];
    const float* W   = (const float*)d_in[2];
    const float* gam = (const float*)d_in[3];
    const float* bet = (const float*)d_in[4];
    const float* mea = (const float*)d_in[5];
    const float* var = (const float*)d_in[6];
    const float* slo = (const float*)d_in[7];
    const float* shi = (const float*)d_in[8];
    const float* pbi = (const float*)d_in[9];
    float* out = (float*)d_out;

    cudaFuncSetAttribute(gemm_kernel, cudaFuncAttributeMaxDynamicSharedMemorySize, SMTOTAL);

    prep_kernel<<<64, 256>>>(W, gam, bet, mea, var);
    sign_w_kernel<<<512, 256>>>(W);
    binarize_kernel<<<dim3(13, 8, 64), 256>>>(x, rb);
    gemm_kernel<<<dim3(4, MTOT / MTILE), 256, SMTOTAL>>>(x, slo, shi, pbi, out);
}